// round 3
// baseline (speedup 1.0000x reference)
#include <cuda_runtime.h>
#include <cuda_fp16.h>
#include <cstdint>
#include <cstddef>

// ============================================================================
// Problem dims (fixed)
// ============================================================================
#define D_IN_   2048
#define D_HID_  8192
#define D_OUT_  2048
#define N_TOK_  8192

// GEMM tile config (sm80-style pipelined mma.sync kernel — the harness compiles
// for plain sm_100, so tcgen05 is unavailable; legacy HMMA path it is)
#define BM 128
#define BN 128
#define BK 32
#define STAGES 4
#define A_STAGE_BYTES (BM * BK * 2)                    // 8192
#define B_STAGE_BYTES (BN * BK * 2)                    // 8192
#define STAGE_BYTES   (A_STAGE_BYTES + B_STAGE_BYTES)  // 16384
#define SMEM_BYTES    (STAGES * STAGE_BYTES)           // 65536

// ============================================================================
// Device scratch (no cudaMalloc allowed)
// ============================================================================
__device__ __align__(128) __half g_A1 [(size_t)N_TOK_ * D_IN_ ];  // x^T  as [M,K]
__device__ __align__(128) __half g_W1T[(size_t)D_HID_ * D_IN_ ];  // W1^T as [N,K]
__device__ __align__(128) __half g_W2T[(size_t)D_OUT_ * D_HID_];  // W2^T as [N,K]
__device__ __align__(128) __half g_h  [(size_t)N_TOK_ * D_HID_];  // gelu(fc1) [M,K]

// ============================================================================
// Helpers
// ============================================================================
__device__ __forceinline__ uint32_t smem_u32(const void* p) {
    uint32_t a;
    asm("{ .reg .u64 t; cvta.to.shared.u64 t, %1; cvt.u32.u64 %0, t; }"
        : "=r"(a) : "l"(p));
    return a;
}

__device__ __forceinline__ float gelu_tanh(float v) {
    // jax.nn.gelu default (approximate=True)
    float t = tanhf(0.7978845608028654f * (v + 0.044715f * v * v * v));
    return 0.5f * v * (1.0f + t);
}

// ============================================================================
// Prep: transpose+convert  in fp32 [R][C]  ->  out fp16 [C][R]
// ============================================================================
__global__ void __launch_bounds__(256)
transpose_f32_to_f16(const float* __restrict__ in, __half* __restrict__ out,
                     int R, int C) {
    __shared__ float tile[32][33];
    const int c0 = blockIdx.x * 32;
    const int r0 = blockIdx.y * 32;
    const int x = threadIdx.x;     // 0..31
    const int y = threadIdx.y;     // 0..7
    #pragma unroll
    for (int k = 0; k < 4; k++)
        tile[y + 8 * k][x] = in[(size_t)(r0 + y + 8 * k) * C + (c0 + x)];
    __syncthreads();
    #pragma unroll
    for (int k = 0; k < 4; k++)
        out[(size_t)(c0 + y + 8 * k) * R + (r0 + x)] =
            __float2half_rn(tile[x][y + 8 * k]);
}

// ============================================================================
// NT GEMM:  C[M,N] = op( A[M,K] * Bt[N,K]^T + bias[N] )
// SMEM rows are 64 B = 4 x 16B units, unit swizzled by u ^= (row>>1)&3
// (conflict-free for the 16B cp.async stores and all fragment LDS.32 loads).
// ============================================================================
template <bool GELU, bool HALF_OUT>
__global__ void __launch_bounds__(256)
gemm_nt(const __half* __restrict__ A, const __half* __restrict__ Bt,
        const float* __restrict__ bias, void* __restrict__ Cout,
        int M, int N, int K) {
    extern __shared__ char smem[];
    const uint32_t sbase = smem_u32(smem);
    const int tid  = threadIdx.x;
    const int wid  = tid >> 5;
    const int lane = tid & 31;
    const int grp  = lane >> 2;            // 0..7
    const int t4   = (lane & 3) * 4;       // byte offset of k-pair in 16B unit
    const int warp_m = (wid & 1) * 64;     // 2 warps along M
    const int warp_n = (wid >> 1) * 32;    // 4 warps along N
    const int m0 = blockIdx.y * BM;
    const int n0 = blockIdx.x * BN;

    float acc[4][4][4];
    #pragma unroll
    for (int mi = 0; mi < 4; mi++)
        #pragma unroll
        for (int ni = 0; ni < 4; ni++)
            #pragma unroll
            for (int r = 0; r < 4; r++) acc[mi][ni][r] = 0.0f;

    // ---- async tile loader: 512 x 16B chunks per operand, 2 per thread ----
    auto issue = [&](int slot, int kblk) {
        const uint32_t sA = sbase + slot * STAGE_BYTES;
        const uint32_t sB = sA + A_STAGE_BYTES;
        const int kofs = kblk * BK;
        #pragma unroll
        for (int h = 0; h < 2; h++) {
            const int q   = tid + h * 256;       // 0..511
            const int row = q >> 2;              // 0..127
            const int u   = q & 3;               // 16B unit in row
            const int up  = u ^ ((row >> 1) & 3);
            const __half* srcA = A  + (size_t)(m0 + row) * K + kofs + u * 8;
            const __half* srcB = Bt + (size_t)(n0 + row) * K + kofs + u * 8;
            asm volatile("cp.async.cg.shared.global [%0], [%1], 16;\n"
                         :: "r"(sA + row * 64 + up * 16), "l"(srcA));
            asm volatile("cp.async.cg.shared.global [%0], [%1], 16;\n"
                         :: "r"(sB + row * 64 + up * 16), "l"(srcB));
        }
    };

    const int NKT = K / BK;

    // ---- prologue: fill STAGES-1 stages ----
    #pragma unroll
    for (int s = 0; s < STAGES - 1; s++) {
        issue(s, s);
        asm volatile("cp.async.commit_group;\n" ::: "memory");
    }

    // ---- mainloop ----
    for (int i = 0; i < NKT; i++) {
        asm volatile("cp.async.wait_group %0;\n" :: "n"(STAGES - 2) : "memory");
        __syncthreads();
        if (i + STAGES - 1 < NKT) issue((i + STAGES - 1) % STAGES, i + STAGES - 1);
        asm volatile("cp.async.commit_group;\n" ::: "memory");

        const char* cA = smem + (i % STAGES) * STAGE_BYTES;
        const char* cB = cA + A_STAGE_BYTES;

        #pragma unroll
        for (int kk = 0; kk < 2; kk++) {        // two k16 chunks per BK=32
            const int u0 = kk * 2, u1 = kk * 2 + 1;
            uint32_t af[4][4];
            #pragma unroll
            for (int mi = 0; mi < 4; mi++) {
                const int r0 = warp_m + mi * 16 + grp;
                const int r1 = r0 + 8;
                const int x0 = (r0 >> 1) & 3, x1 = (r1 >> 1) & 3;
                af[mi][0] = *(const uint32_t*)(cA + r0 * 64 + ((u0 ^ x0) << 4) + t4);
                af[mi][1] = *(const uint32_t*)(cA + r1 * 64 + ((u0 ^ x1) << 4) + t4);
                af[mi][2] = *(const uint32_t*)(cA + r0 * 64 + ((u1 ^ x0) << 4) + t4);
                af[mi][3] = *(const uint32_t*)(cA + r1 * 64 + ((u1 ^ x1) << 4) + t4);
            }
            uint32_t bf[4][2];
            #pragma unroll
            for (int ni = 0; ni < 4; ni++) {
                const int rn = warp_n + ni * 8 + grp;
                const int xn = (rn >> 1) & 3;
                bf[ni][0] = *(const uint32_t*)(cB + rn * 64 + ((u0 ^ xn) << 4) + t4);
                bf[ni][1] = *(const uint32_t*)(cB + rn * 64 + ((u1 ^ xn) << 4) + t4);
            }
            #pragma unroll
            for (int mi = 0; mi < 4; mi++)
                #pragma unroll
                for (int ni = 0; ni < 4; ni++)
                    asm volatile(
                        "mma.sync.aligned.m16n8k16.row.col.f32.f16.f16.f32 "
                        "{%0,%1,%2,%3}, {%4,%5,%6,%7}, {%8,%9}, {%0,%1,%2,%3};\n"
                        : "+f"(acc[mi][ni][0]), "+f"(acc[mi][ni][1]),
                          "+f"(acc[mi][ni][2]), "+f"(acc[mi][ni][3])
                        : "r"(af[mi][0]), "r"(af[mi][1]),
                          "r"(af[mi][2]), "r"(af[mi][3]),
                          "r"(bf[ni][0]), "r"(bf[ni][1]));
        }
    }

    // ---- epilogue: bias (+gelu), store ----
    // C frag map: c0,c1 -> (row grp, col 2t,2t+1); c2,c3 -> (row grp+8, same cols)
    #pragma unroll
    for (int mi = 0; mi < 4; mi++) {
        const int rm = m0 + warp_m + mi * 16 + grp;
        #pragma unroll
        for (int ni = 0; ni < 4; ni++) {
            const int cn = n0 + warp_n + ni * 8 + ((lane & 3) << 1);
            const float2 bv = *(const float2*)(bias + cn);
            float v0 = acc[mi][ni][0] + bv.x;
            float v1 = acc[mi][ni][1] + bv.y;
            float v2 = acc[mi][ni][2] + bv.x;
            float v3 = acc[mi][ni][3] + bv.y;
            if (GELU) {
                v0 = gelu_tanh(v0); v1 = gelu_tanh(v1);
                v2 = gelu_tanh(v2); v3 = gelu_tanh(v3);
            }
            if (HALF_OUT) {
                __half* O = (__half*)Cout;
                *(__half2*)(O + (size_t)rm * N + cn) = __floats2half2_rn(v0, v1);
                *(__half2*)(O + (size_t)(rm + 8) * N + cn) = __floats2half2_rn(v2, v3);
            } else {
                float* O = (float*)Cout;
                *(float2*)(O + (size_t)rm * N + cn) = make_float2(v0, v1);
                *(float2*)(O + (size_t)(rm + 8) * N + cn) = make_float2(v2, v3);
            }
        }
    }
}

// ============================================================================
// Launch
// ============================================================================
extern "C" void kernel_launch(void* const* d_in, const int* in_sizes, int n_in,
                              void* d_out, int out_size) {
    (void)in_sizes; (void)n_in; (void)out_size;
    const float* x  = (const float*)d_in[0];   // [D_IN,  N_TOK]
    const float* W1 = (const float*)d_in[1];   // [D_IN,  D_HID]
    const float* b1 = (const float*)d_in[2];   // [D_HID]
    const float* W2 = (const float*)d_in[3];   // [D_HID, D_OUT]
    const float* b2 = (const float*)d_in[4];   // [D_OUT]
    float* out = (float*)d_out;                // [N_TOK, D_OUT]

    __half *A1, *W1T, *W2T, *h;
    cudaGetSymbolAddress((void**)&A1,  g_A1);
    cudaGetSymbolAddress((void**)&W1T, g_W1T);
    cudaGetSymbolAddress((void**)&W2T, g_W2T);
    cudaGetSymbolAddress((void**)&h,   g_h);

    cudaFuncSetAttribute(gemm_nt<true,  true>,
                         cudaFuncAttributeMaxDynamicSharedMemorySize, SMEM_BYTES);
    cudaFuncSetAttribute(gemm_nt<false, false>,
                         cudaFuncAttributeMaxDynamicSharedMemorySize, SMEM_BYTES);

    const dim3 tb(32, 8);
    // x  [2048][8192] -> A1  [8192][2048]
    transpose_f32_to_f16<<<dim3(N_TOK_ / 32, D_IN_ / 32), tb>>>(x, A1, D_IN_, N_TOK_);
    // W1 [2048][8192] -> W1T [8192][2048]
    transpose_f32_to_f16<<<dim3(D_HID_ / 32, D_IN_ / 32), tb>>>(W1, W1T, D_IN_, D_HID_);
    // W2 [8192][2048] -> W2T [2048][8192]
    transpose_f32_to_f16<<<dim3(D_OUT_ / 32, D_HID_ / 32), tb>>>(W2, W2T, D_HID_, D_OUT_);

    // GEMM1: h = gelu(A1 · W1T^T + b1)    [8192 x 8192], K = 2048
    gemm_nt<true, true>
        <<<dim3(D_HID_ / BN, N_TOK_ / BM), 256, SMEM_BYTES>>>(
            A1, W1T, b1, h, N_TOK_, D_HID_, D_IN_);

    // GEMM2: out = h · W2T^T + b2         [8192 x 2048], K = 8192
    gemm_nt<false, false>
        <<<dim3(D_OUT_ / BN, N_TOK_ / BM), 256, SMEM_BYTES>>>(
            h, W2T, b2, out, N_TOK_, D_OUT_, D_HID_);
}

// round 5
// speedup vs baseline: 1.3158x; 1.3158x over previous
#include <cuda_runtime.h>
#include <cuda_fp16.h>
#include <cstdint>
#include <cstddef>

// ============================================================================
// Problem dims (fixed)
// ============================================================================
#define D_IN_   2048
#define D_HID_  8192
#define D_OUT_  2048
#define N_TOK_  8192

// GEMM tile config (sm80-style pipelined mma.sync kernel — the harness compiles
// for plain sm_100, so tcgen05 is unavailable; legacy HMMA path it is)
#define BM 128
#define BN 128
#define BK 32
#define STAGES 5
#define A_STAGE_BYTES (BM * BK * 2)                    // 8192
#define B_STAGE_BYTES (BN * BK * 2)                    // 8192
#define STAGE_BYTES   (A_STAGE_BYTES + B_STAGE_BYTES)  // 16384
#define SMEM_BYTES    (STAGES * STAGE_BYTES)           // 81920 (x2 CTAs = 160KB)

// ============================================================================
// Device scratch (no cudaMalloc allowed)
// ============================================================================
__device__ __align__(128) __half g_A1 [(size_t)N_TOK_ * D_IN_ ];  // x^T  as [M,K]
__device__ __align__(128) __half g_W1T[(size_t)D_HID_ * D_IN_ ];  // W1^T as [N,K]
__device__ __align__(128) __half g_W2T[(size_t)D_OUT_ * D_HID_];  // W2^T as [N,K]
__device__ __align__(128) __half g_h  [(size_t)N_TOK_ * D_HID_];  // gelu(fc1) [M,K]

// ============================================================================
// Helpers
// ============================================================================
__device__ __forceinline__ uint32_t smem_u32(const void* p) {
    uint32_t a;
    asm("{ .reg .u64 t; cvta.to.shared.u64 t, %1; cvt.u32.u64 %0, t; }"
        : "=r"(a) : "l"(p));
    return a;
}

__device__ __forceinline__ float gelu_tanh(float v) {
    // jax.nn.gelu default (approximate=True)
    float t = tanhf(0.7978845608028654f * (v + 0.044715f * v * v * v));
    return 0.5f * v * (1.0f + t);
}

#define LDSM_X4(r0, r1, r2, r3, addr) \
    asm volatile("ldmatrix.sync.aligned.m8n8.x4.shared.b16 {%0,%1,%2,%3}, [%4];" \
        : "=r"(r0), "=r"(r1), "=r"(r2), "=r"(r3) : "r"(addr))

// ============================================================================
// Prep: transpose+convert  in fp32 [R][C]  ->  out fp16 [C][R]
// ============================================================================
__global__ void __launch_bounds__(256)
transpose_f32_to_f16(const float* __restrict__ in, __half* __restrict__ out,
                     int R, int C) {
    __shared__ float tile[32][33];
    const int c0 = blockIdx.x * 32;
    const int r0 = blockIdx.y * 32;
    const int x = threadIdx.x;     // 0..31
    const int y = threadIdx.y;     // 0..7
    #pragma unroll
    for (int k = 0; k < 4; k++)
        tile[y + 8 * k][x] = in[(size_t)(r0 + y + 8 * k) * C + (c0 + x)];
    __syncthreads();
    #pragma unroll
    for (int k = 0; k < 4; k++)
        out[(size_t)(c0 + y + 8 * k) * R + (r0 + x)] =
            __float2half_rn(tile[x][y + 8 * k]);
}

// ============================================================================
// NT GEMM:  C[M,N] = op( A[M,K] * Bt[N,K]^T + bias[N] )
// SMEM rows are 64 B = 4 x 16B units, unit swizzled by u ^= (row>>1)&3
// (conflict-free for 16B cp.async stores and for ldmatrix: each 8x8 matrix's
//  8 rows cover 32 distinct banks).
// All swizzle math is hoisted: the XOR term is invariant under row += 16k,
// so each thread precomputes 2 A-unit-offsets and 2 B-unit-offsets once.
// ============================================================================
template <bool GELU, bool HALF_OUT>
__global__ void __launch_bounds__(256, 2)
gemm_nt(const __half* __restrict__ A, const __half* __restrict__ Bt,
        const float* __restrict__ bias, void* __restrict__ Cout,
        int M, int N, int K) {
    extern __shared__ char smem[];
    const uint32_t sbase = smem_u32(smem);
    const int tid  = threadIdx.x;
    const int wid  = tid >> 5;
    const int lane = tid & 31;
    const int grp  = lane >> 2;            // 0..7 (epilogue row group)
    const int g8   = lane >> 3;            // 0..3 (ldmatrix address group)
    const int warp_m = (wid & 1) * 64;     // 2 warps along M
    const int warp_n = (wid >> 1) * 32;    // 4 warps along N
    const int m0 = blockIdx.y * BM;
    const int n0 = blockIdx.x * BN;

    // ---- precomputed ldmatrix addresses (byte offsets within a stage) ----
    // A x4 for tile mi: matrices (rows 0-7,u0)(rows 8-15,u0)(rows 0-7,u1)(rows 8-15,u1)
    //   lane group g8: row_off = (g8&1)*8 + lane&7,  unit = 2*kk + (g8>>1)
    const int a_row = warp_m + (g8 & 1) * 8 + (lane & 7);
    const int xrA   = (a_row >> 1) & 3;            // invariant under +16*mi
    const uint32_t a_base   = (uint32_t)a_row * 64;
    const uint32_t soA0 = (uint32_t)(((g8 >> 1) ^ xrA) << 4);
    const uint32_t soA1 = (uint32_t)(((2 + (g8 >> 1)) ^ xrA) << 4);
    // B x4 for ni-pair p: matrices (ntile p0,u0)(p0,u1)(ntile p1,u0)(p1,u1)
    //   lane group g8: n-tile = g8>>1, unit = 2*kk + (g8&1)
    const int b_row = warp_n + (g8 >> 1) * 8 + (lane & 7);
    const int xrB   = (b_row >> 1) & 3;            // invariant under +16*p
    const uint32_t b_base   = (uint32_t)b_row * 64;
    const uint32_t soB0 = (uint32_t)(((g8 & 1) ^ xrB) << 4);
    const uint32_t soB1 = (uint32_t)(((2 + (g8 & 1)) ^ xrB) << 4);

    float acc[4][4][4];
    #pragma unroll
    for (int mi = 0; mi < 4; mi++)
        #pragma unroll
        for (int ni = 0; ni < 4; ni++)
            #pragma unroll
            for (int r = 0; r < 4; r++) acc[mi][ni][r] = 0.0f;

    // ---- async tile loader: 512 x 16B chunks per operand, 2 per thread ----
    auto issue = [&](int slot, int kblk) {
        const uint32_t sA = sbase + slot * STAGE_BYTES;
        const uint32_t sB = sA + A_STAGE_BYTES;
        const int kofs = kblk * BK;
        #pragma unroll
        for (int h = 0; h < 2; h++) {
            const int q   = tid + h * 256;       // 0..511
            const int row = q >> 2;              // 0..127
            const int u   = q & 3;               // 16B unit in row
            const int up  = u ^ ((row >> 1) & 3);
            const __half* srcA = A  + (size_t)(m0 + row) * K + kofs + u * 8;
            const __half* srcB = Bt + (size_t)(n0 + row) * K + kofs + u * 8;
            asm volatile("cp.async.cg.shared.global [%0], [%1], 16;\n"
                         :: "r"(sA + row * 64 + up * 16), "l"(srcA));
            asm volatile("cp.async.cg.shared.global [%0], [%1], 16;\n"
                         :: "r"(sB + row * 64 + up * 16), "l"(srcB));
        }
    };

    const int NKT = K / BK;

    // ---- prologue: fill STAGES-1 stages ----
    #pragma unroll
    for (int s = 0; s < STAGES - 1; s++) {
        issue(s, s);
        asm volatile("cp.async.commit_group;\n" ::: "memory");
    }

    // ---- mainloop ----
    int slot = 0;
    for (int i = 0; i < NKT; i++) {
        asm volatile("cp.async.wait_group %0;\n" :: "n"(STAGES - 2) : "memory");
        __syncthreads();
        if (i + STAGES - 1 < NKT) issue((i + STAGES - 1) % STAGES, i + STAGES - 1);
        asm volatile("cp.async.commit_group;\n" ::: "memory");

        const uint32_t cA = sbase + slot * STAGE_BYTES;
        const uint32_t cB = cA + A_STAGE_BYTES;
        slot = (slot + 1 == STAGES) ? 0 : slot + 1;

        #pragma unroll
        for (int kk = 0; kk < 2; kk++) {        // two k16 chunks per BK=32
            const uint32_t aoff = cA + a_base + (kk ? soA1 : soA0);
            const uint32_t boff = cB + b_base + (kk ? soB1 : soB0);
            uint32_t af[4][4];
            #pragma unroll
            for (int mi = 0; mi < 4; mi++)
                LDSM_X4(af[mi][0], af[mi][1], af[mi][2], af[mi][3],
                        aoff + mi * 1024);        // 16 rows * 64 B
            uint32_t bf[4][2];
            #pragma unroll
            for (int p = 0; p < 2; p++)
                LDSM_X4(bf[2 * p][0], bf[2 * p][1], bf[2 * p + 1][0], bf[2 * p + 1][1],
                        boff + p * 1024);
            #pragma unroll
            for (int mi = 0; mi < 4; mi++)
                #pragma unroll
                for (int ni = 0; ni < 4; ni++)
                    asm volatile(
                        "mma.sync.aligned.m16n8k16.row.col.f32.f16.f16.f32 "
                        "{%0,%1,%2,%3}, {%4,%5,%6,%7}, {%8,%9}, {%0,%1,%2,%3};\n"
                        : "+f"(acc[mi][ni][0]), "+f"(acc[mi][ni][1]),
                          "+f"(acc[mi][ni][2]), "+f"(acc[mi][ni][3])
                        : "r"(af[mi][0]), "r"(af[mi][1]),
                          "r"(af[mi][2]), "r"(af[mi][3]),
                          "r"(bf[ni][0]), "r"(bf[ni][1]));
        }
    }

    // ---- epilogue: bias (+gelu), store ----
    // C frag map: c0,c1 -> (row grp, col 2t,2t+1); c2,c3 -> (row grp+8, same cols)
    #pragma unroll
    for (int mi = 0; mi < 4; mi++) {
        const int rm = m0 + warp_m + mi * 16 + grp;
        #pragma unroll
        for (int ni = 0; ni < 4; ni++) {
            const int cn = n0 + warp_n + ni * 8 + ((lane & 3) << 1);
            const float2 bv = *(const float2*)(bias + cn);
            float v0 = acc[mi][ni][0] + bv.x;
            float v1 = acc[mi][ni][1] + bv.y;
            float v2 = acc[mi][ni][2] + bv.x;
            float v3 = acc[mi][ni][3] + bv.y;
            if (GELU) {
                v0 = gelu_tanh(v0); v1 = gelu_tanh(v1);
                v2 = gelu_tanh(v2); v3 = gelu_tanh(v3);
            }
            if (HALF_OUT) {
                __half* O = (__half*)Cout;
                *(__half2*)(O + (size_t)rm * N + cn) = __floats2half2_rn(v0, v1);
                *(__half2*)(O + (size_t)(rm + 8) * N + cn) = __floats2half2_rn(v2, v3);
            } else {
                float* O = (float*)Cout;
                *(float2*)(O + (size_t)rm * N + cn) = make_float2(v0, v1);
                *(float2*)(O + (size_t)(rm + 8) * N + cn) = make_float2(v2, v3);
            }
        }
    }
}

// ============================================================================
// Launch
// ============================================================================
extern "C" void kernel_launch(void* const* d_in, const int* in_sizes, int n_in,
                              void* d_out, int out_size) {
    (void)in_sizes; (void)n_in; (void)out_size;
    const float* x  = (const float*)d_in[0];   // [D_IN,  N_TOK]
    const float* W1 = (const float*)d_in[1];   // [D_IN,  D_HID]
    const float* b1 = (const float*)d_in[2];   // [D_HID]
    const float* W2 = (const float*)d_in[3];   // [D_HID, D_OUT]
    const float* b2 = (const float*)d_in[4];   // [D_OUT]
    float* out = (float*)d_out;                // [N_TOK, D_OUT]

    __half *A1, *W1T, *W2T, *h;
    cudaGetSymbolAddress((void**)&A1,  g_A1);
    cudaGetSymbolAddress((void**)&W1T, g_W1T);
    cudaGetSymbolAddress((void**)&W2T, g_W2T);
    cudaGetSymbolAddress((void**)&h,   g_h);

    cudaFuncSetAttribute(gemm_nt<true,  true>,
                         cudaFuncAttributeMaxDynamicSharedMemorySize, SMEM_BYTES);
    cudaFuncSetAttribute(gemm_nt<false, false>,
                         cudaFuncAttributeMaxDynamicSharedMemorySize, SMEM_BYTES);

    const dim3 tb(32, 8);
    // x  [2048][8192] -> A1  [8192][2048]
    transpose_f32_to_f16<<<dim3(N_TOK_ / 32, D_IN_ / 32), tb>>>(x, A1, D_IN_, N_TOK_);
    // W1 [2048][8192] -> W1T [8192][2048]
    transpose_f32_to_f16<<<dim3(D_HID_ / 32, D_IN_ / 32), tb>>>(W1, W1T, D_IN_, D_HID_);
    // W2 [8192][2048] -> W2T [2048][8192]
    transpose_f32_to_f16<<<dim3(D_OUT_ / 32, D_HID_ / 32), tb>>>(W2, W2T, D_HID_, D_OUT_);

    // GEMM1: h = gelu(A1 · W1T^T + b1)    [8192 x 8192], K = 2048
    gemm_nt<true, true>
        <<<dim3(D_HID_ / BN, N_TOK_ / BM), 256, SMEM_BYTES>>>(
            A1, W1T, b1, h, N_TOK_, D_HID_, D_IN_);

    // GEMM2: out = h · W2T^T + b2         [8192 x 2048], K = 8192
    gemm_nt<false, false>
        <<<dim3(D_OUT_ / BN, N_TOK_ / BM), 256, SMEM_BYTES>>>(
            h, W2T, b2, out, N_TOK_, D_OUT_, D_HID_);
}